// round 10
// baseline (speedup 1.0000x reference)
#include <cuda_runtime.h>
#include <math.h>

#define B_SZ   8
#define L_SZ   2048
#define D_HALF 256
#define D_TYPE 32
#define HID    544          // 512 positional + 32 type
#define NTYPES 21           // NUM_TYPES + 1 (padding row 0)
#define NPAIR  (NTYPES * NTYPES)   // 441
#define TI     64
#define TJ     128
#define HROWS  8            // hidden rows per block
#define PAIR_BLOCKS (B_SZ * (L_SZ / TI) * (L_SZ / TJ))   // 4096
#define HIDDEN_BLOCKS (B_SZ * L_SZ / HROWS)              // 2048
#define TOTAL_BLOCKS (PAIR_BLOCKS + HIDDEN_BLOCKS)       // 6144 = 3*2048

// fp32 constant matching reference: -log(10000.0)/512 rounded to f32
#define DIV_C  (-0.017988946f)

// -------- fused single launch: pair tiles + multi-row hidden blocks ------
__global__ void __launch_bounds__(256) fused_kernel(
    const int* __restrict__ etype,
    const float* __restrict__ etime,
    const float* __restrict__ Wt,
    const float* __restrict__ temb,
    const float* __restrict__ wl,
    const float* __restrict__ wg,
    const float* __restrict__ p_bl,
    const float* __restrict__ p_bg,
    float* __restrict__ out_scores,
    float* __restrict__ out_hidden,
    float* __restrict__ out_tdiff) {

    int bid = blockIdx.x;
    int tid = threadIdx.x;
    int q   = bid / 3;
    int rem = bid - q * 3;

    if (rem == 2) {
        // ---------------- hidden branch: HROWS positions per block -------
        int bl0 = q * HROWS;                 // first b*L + l of this block
        int k   = tid;                       // 0..255
        // div_term, matches ref: f32 exp of f32 product (precise expf)
        float dv = expf((float)(2 * k) * DIV_C);
        float wt = Wt[k];
        float* o = out_hidden + (unsigned)bl0 * HID + k;
#pragma unroll
        for (int rr = 0; rr < HROWS; ++rr) {
            int bl = bl0 + rr;
            int l  = bl & (L_SZ - 1);
            float t   = etime[bl];
            float arc = (float)l * dv;       // same fp32 product as reference
            float x   = arc + t * wt;

            // Cody-Waite reduction x mod 2*pi  (|x| < 2100, n < 340)
            float n = rintf(x * 0.15915494309189535f);
            float r = fmaf(n, -6.28125f, x);             // C1 exact in binary
            r = fmaf(n, -1.9353071795864769e-3f, r);     // C2
            float s, c;
            __sincosf(r, &s, &c);

            o[0]      = s;
            o[D_HALF] = c;
            if (k < D_TYPE)
                o[2 * D_HALF] = temb[etype[bl] * D_TYPE + k];
            o += HID;
        }
        return;
    }

    // ---------------- pair branch ----------------
    int p  = q * 2 + rem;        // 0..4095
    int jx = p & 15;             // 16 tiles of TJ=128
    int iy = (p >> 4) & 31;      // 32 tiles of TI=64
    int b  = p >> 9;             // 8 batches
    int i0 = iy * TI;
    int j0 = jx * TJ;

    __shared__ float  s_tj[TJ], s_ti[TI];
    __shared__ int    s_etj[TJ], s_eti[TI];
    __shared__ float  dA[NTYPES], dB[NTYPES], gA[NTYPES], gB[NTYPES];
    __shared__ float2 s_tab[NPAIR];

    int off = b * L_SZ;
    bool zero_tile = (j0 >= i0 + TI);      // entire tile j >= i -> scores 0
    bool full_tile = (j0 + TJ <= i0);      // entire tile j <  i -> no mask

    if (tid < TJ) {
        int j = j0 + tid;
        s_tj[tid]  = etime[off + j];
        s_etj[tid] = etype[off + j];
    } else if (tid < TJ + TI) {
        int il = tid - TJ;
        int i  = i0 + il;
        s_ti[il]  = etime[off + i];
        s_eti[il] = etype[off + i] * NTYPES;
    }
    // stage 1 of table build: 84 per-type dots (skipped for zero tiles)
    if (!zero_tile && tid < 4 * NTYPES) {
        int ty    = tid >> 2;            // type 0..20
        int which = tid & 3;             // 0:dA 1:dB 2:gA 3:gB
        const float4* te = (const float4*)(temb + ty * D_TYPE);
        const float4* w  = (const float4*)((which < 2 ? wl : wg) + (which & 1) * D_TYPE);
        float acc = 0.f;
#pragma unroll
        for (int k = 0; k < D_TYPE / 4; ++k) {
            float4 tv = te[k], wv = w[k];
            acc += tv.x * wv.x + tv.y * wv.y + tv.z * wv.z + tv.w * wv.w;
        }
        if      (which == 0) dA[ty] = acc;
        else if (which == 1) dB[ty] = acc;
        else if (which == 2) gA[ty] = acc;
        else                 gB[ty] = acc;
    }
    __syncthreads();

    int jq = tid & 31;       // 32 quads of j (float4)
    int ir = tid >> 5;       // 8 row groups
    int jj = jq * 4;

    float4 tj = *(const float4*)&s_tj[jj];
    unsigned base = (unsigned)(off + i0) * L_SZ + (unsigned)(j0 + jj);

    // ---- pass A: stream t_diff (needs no table); zero tiles also stream
    //      zero scores and exit with a single barrier.
    if (zero_tile) {
        float4 z = make_float4(0.f, 0.f, 0.f, 0.f);
#pragma unroll
        for (int r = 0; r < TI / 8; ++r) {
            int il = ir + r * 8;
            float ti = s_ti[il];
            float4 td;
            td.x = fabsf(tj.x - ti);
            td.y = fabsf(tj.y - ti);
            td.z = fabsf(tj.z - ti);
            td.w = fabsf(tj.w - ti);
            unsigned ofs = base + (unsigned)il * L_SZ;
            __stcs((float4*)(out_tdiff  + ofs), td);
            __stcs((float4*)(out_scores + ofs), z);
        }
        return;
    }

#pragma unroll
    for (int r = 0; r < TI / 8; ++r) {
        int il = ir + r * 8;
        float ti = s_ti[il];
        float4 td;
        td.x = fabsf(tj.x - ti);
        td.y = fabsf(tj.y - ti);
        td.z = fabsf(tj.z - ti);
        td.w = fabsf(tj.w - ti);
        __stcs((float4*)(out_tdiff + base + (unsigned)il * L_SZ), td);
    }

    // ---- stage 2: 441 table entries (overlaps pass-A store drain) ----
    {
        float BLv = __ldg(p_bl);
        float BGv = __ldg(p_bg);
        for (int w = tid; w < NPAIR; w += 256) {
            int t_i = w / NTYPES;
            int t_j = w - t_i * NTYPES;
            float xl = dA[t_j] + dB[t_i] + BLv;
            float sp = fmaxf(xl, 0.f) + __logf(1.f + __expf(-fabsf(xl)));
            float xg = 5.f * (gA[t_j] + gB[t_i] + BGv);
            s_tab[w] = make_float2(__fdividef(1.f, sp + 1e-6f),
                                   __fdividef(1.f, 1.f + __expf(-xg)));
        }
    }
    __syncthreads();

    int4 ej = *(const int4*)&s_etj[jj];

    // ---- pass B: scores (td recomputed: 1 sub + abs per element) ----
#pragma unroll
    for (int r = 0; r < TI / 8; ++r) {
        int il = ir + r * 8;
        float ti = s_ti[il];
        float4 td;
        td.x = fabsf(tj.x - ti);
        td.y = fabsf(tj.y - ti);
        td.z = fabsf(tj.z - ti);
        td.w = fabsf(tj.w - ti);

        int rb = s_eti[il];
        float2 cx = s_tab[rb + ej.x];
        float2 cy = s_tab[rb + ej.y];
        float2 cz = s_tab[rb + ej.z];
        float2 cw = s_tab[rb + ej.w];
        float ux = td.x * cx.x;
        float uy = td.y * cy.x;
        float uz = td.z * cz.x;
        float uw = td.w * cw.x;
        float4 sv;
        sv.x = cx.y * (0.4f * __expf(-0.5f * ux * ux) + 0.3f * __expf(-ux));
        sv.y = cy.y * (0.4f * __expf(-0.5f * uy * uy) + 0.3f * __expf(-uy));
        sv.z = cz.y * (0.4f * __expf(-0.5f * uz * uz) + 0.3f * __expf(-uz));
        sv.w = cw.y * (0.4f * __expf(-0.5f * uw * uw) + 0.3f * __expf(-uw));
        if (!full_tile) {
            int i = i0 + il;
            int j = j0 + jj;
            if (j     >= i) sv.x = 0.f;
            if (j + 1 >= i) sv.y = 0.f;
            if (j + 2 >= i) sv.z = 0.f;
            if (j + 3 >= i) sv.w = 0.f;
        }
        __stcs((float4*)(out_scores + base + (unsigned)il * L_SZ), sv);
    }
}

extern "C" void kernel_launch(void* const* d_in, const int* in_sizes, int n_in,
                              void* d_out, int out_size) {
    const int*   etype = (const int*)  d_in[0];
    const float* etime = (const float*)d_in[1];
    // d_in[2] = arrival_times (unused by reference)
    const float* Wt    = (const float*)d_in[3];
    const float* temb  = (const float*)d_in[4];
    const float* wl    = (const float*)d_in[5];
    const float* p_bl  = (const float*)d_in[6];
    const float* wg    = (const float*)d_in[7];
    const float* p_bg  = (const float*)d_in[8];

    float* out = (float*)d_out;
    const size_t scoresN = (size_t)B_SZ * L_SZ * L_SZ;
    const size_t hidN    = (size_t)B_SZ * L_SZ * HID;
    float* out_scores = out;
    float* out_hidden = out + scoresN;
    float* out_tdiff  = out + scoresN + hidN;

    fused_kernel<<<TOTAL_BLOCKS, 256>>>(
        etype, etime, Wt, temb, wl, wg, p_bl, p_bg,
        out_scores, out_hidden, out_tdiff);
}

// round 11
// speedup vs baseline: 1.0116x; 1.0116x over previous
#include <cuda_runtime.h>
#include <math.h>

#define B_SZ   8
#define L_SZ   2048
#define D_HALF 256
#define D_TYPE 32
#define HID    544          // 512 positional + 32 type
#define NTYPES 21           // NUM_TYPES + 1 (padding row 0)
#define NPAIR  (NTYPES * NTYPES)   // 441
#define TI     64
#define TJ     128
#define HROWS  8            // hidden rows per block
#define PAIR_BLOCKS (B_SZ * (L_SZ / TI) * (L_SZ / TJ))   // 4096
#define HIDDEN_BLOCKS (B_SZ * L_SZ / HROWS)              // 2048
#define TOTAL_BLOCKS (PAIR_BLOCKS + HIDDEN_BLOCKS)       // 6144 = 3*2048

// fp32 constant matching reference: -log(10000.0)/512 rounded to f32
#define DIV_C  (-0.017988946f)

// -------- fused single launch: pair tiles + multi-row hidden blocks ------
__global__ void __launch_bounds__(256, 6) fused_kernel(
    const int* __restrict__ etype,
    const float* __restrict__ etime,
    const float* __restrict__ Wt,
    const float* __restrict__ temb,
    const float* __restrict__ wl,
    const float* __restrict__ wg,
    const float* __restrict__ p_bl,
    const float* __restrict__ p_bg,
    float* __restrict__ out_scores,
    float* __restrict__ out_hidden,
    float* __restrict__ out_tdiff) {

    int bid = blockIdx.x;
    int tid = threadIdx.x;
    int q   = bid / 3;
    int rem = bid - q * 3;

    if (rem == 2) {
        // ---------------- hidden branch: HROWS positions per block -------
        int bl0 = q * HROWS;                 // first b*L + l of this block
        int k   = tid;                       // 0..255
        // div_term, matches ref: f32 exp of f32 product (precise expf)
        float dv = expf((float)(2 * k) * DIV_C);
        float wt = Wt[k];
        float* o = out_hidden + (unsigned)bl0 * HID + k;
#pragma unroll
        for (int rr = 0; rr < HROWS; ++rr) {
            int bl = bl0 + rr;
            int l  = bl & (L_SZ - 1);
            float t   = etime[bl];
            float arc = (float)l * dv;       // same fp32 product as reference
            float x   = arc + t * wt;

            // Cody-Waite reduction x mod 2*pi  (|x| < 2100, n < 340)
            float n = rintf(x * 0.15915494309189535f);
            float r = fmaf(n, -6.28125f, x);             // C1 exact in binary
            r = fmaf(n, -1.9353071795864769e-3f, r);     // C2
            float s, c;
            __sincosf(r, &s, &c);

            o[0]      = s;
            o[D_HALF] = c;
            if (k < D_TYPE)
                o[2 * D_HALF] = temb[etype[bl] * D_TYPE + k];
            o += HID;
        }
        return;
    }

    // ---------------- pair branch ----------------
    int p  = q * 2 + rem;        // 0..4095
    int jx = p & 15;             // 16 tiles of TJ=128
    int iy = (p >> 4) & 31;      // 32 tiles of TI=64
    int b  = p >> 9;             // 8 batches
    int i0 = iy * TI;
    int j0 = jx * TJ;

    __shared__ float  s_tj[TJ], s_ti[TI];
    __shared__ int    s_etj[TJ], s_eti[TI];
    __shared__ float  dA[NTYPES], dB[NTYPES], gA[NTYPES], gB[NTYPES];
    __shared__ float2 s_tab[NPAIR];   // (rl, 0.4*gt) ; 0.3*gt derived by scale

    int off = b * L_SZ;
    bool zero_tile = (j0 >= i0 + TI);      // entire tile j >= i -> scores 0
    bool full_tile = (j0 + TJ <= i0);      // entire tile j <  i -> no mask

    if (tid < TJ) {
        int j = j0 + tid;
        s_tj[tid]  = etime[off + j];
        s_etj[tid] = etype[off + j];
    } else if (tid < TJ + TI) {
        int il = tid - TJ;
        int i  = i0 + il;
        s_ti[il]  = etime[off + i];
        s_eti[il] = etype[off + i] * NTYPES;
    }

    if (!zero_tile) {
        // ---- per-block table build stage 1: 84 per-type dots ----
        if (tid < 4 * NTYPES) {
            int ty    = tid >> 2;            // type 0..20
            int which = tid & 3;             // 0:dA 1:dB 2:gA 3:gB
            const float4* te = (const float4*)(temb + ty * D_TYPE);
            const float4* w  = (const float4*)((which < 2 ? wl : wg) + (which & 1) * D_TYPE);
            float acc = 0.f;
#pragma unroll
            for (int k = 0; k < D_TYPE / 4; ++k) {
                float4 tv = te[k], wv = w[k];
                acc += tv.x * wv.x + tv.y * wv.y + tv.z * wv.z + tv.w * wv.w;
            }
            if      (which == 0) dA[ty] = acc;
            else if (which == 1) dB[ty] = acc;
            else if (which == 2) gA[ty] = acc;
            else                 gB[ty] = acc;
        }
        __syncthreads();
        // ---- stage 2: 441 fused entries (rl, 0.4*gt) ----
        float BLv = __ldg(p_bl);
        float BGv = __ldg(p_bg);
        for (int w = tid; w < NPAIR; w += 256) {
            int t_i = w / NTYPES;
            int t_j = w - t_i * NTYPES;
            float xl = dA[t_j] + dB[t_i] + BLv;
            float sp = fmaxf(xl, 0.f) + __logf(1.f + __expf(-fabsf(xl)));
            float xg = 5.f * (gA[t_j] + gB[t_i] + BGv);
            float gt = __fdividef(1.f, 1.f + __expf(-xg));
            s_tab[w] = make_float2(__fdividef(1.f, sp + 1e-6f), 0.4f * gt);
        }
    }
    __syncthreads();

    int jq = tid & 31;       // 32 quads of j (float4)
    int ir = tid >> 5;       // 8 row groups
    int jj = jq * 4;

    float4 tj = *(const float4*)&s_tj[jj];
    int4   ej = *(const int4*)&s_etj[jj];

    // per-thread mask thresholds: element (il, jj+c) masked when j0+jj+c >= i0+il
    // i.e. il <= jj + c + (j0 - i0). Compare il against mthr+c once per row.
    int mthr = jj + j0 - i0;

    unsigned base = (unsigned)(off + i0) * L_SZ + (unsigned)(j0 + jj);

#pragma unroll
    for (int r = 0; r < TI / 8; ++r) {
        int il = ir + r * 8;
        float ti = s_ti[il];
        float4 td;
        td.x = fabsf(tj.x - ti);
        td.y = fabsf(tj.y - ti);
        td.z = fabsf(tj.z - ti);
        td.w = fabsf(tj.w - ti);

        float4 sv;
        if (zero_tile) {
            sv = make_float4(0.f, 0.f, 0.f, 0.f);
        } else {
            int rb = s_eti[il];
            float2 cx = s_tab[rb + ej.x];
            float2 cy = s_tab[rb + ej.y];
            float2 cz = s_tab[rb + ej.z];
            float2 cw = s_tab[rb + ej.w];
            float ux = td.x * cx.x;
            float uy = td.y * cy.x;
            float uz = td.z * cz.x;
            float uw = td.w * cw.x;
            // gt*(0.4*kse + 0.3*kex) = (0.4gt)*kse + 0.75*(0.4gt)*kex
            sv.x = cx.y * __expf(-0.5f * ux * ux) + 0.75f * cx.y * __expf(-ux);
            sv.y = cy.y * __expf(-0.5f * uy * uy) + 0.75f * cy.y * __expf(-uy);
            sv.z = cz.y * __expf(-0.5f * uz * uz) + 0.75f * cz.y * __expf(-uz);
            sv.w = cw.y * __expf(-0.5f * uw * uw) + 0.75f * cw.y * __expf(-uw);
            if (!full_tile) {
                if (il <= mthr    ) sv.x = 0.f;
                if (il <= mthr + 1) sv.y = 0.f;
                if (il <= mthr + 2) sv.z = 0.f;
                if (il <= mthr + 3) sv.w = 0.f;
            }
        }
        unsigned ofs = base + (unsigned)il * L_SZ;
        __stcs((float4*)(out_scores + ofs), sv);
        __stcs((float4*)(out_tdiff  + ofs), td);
    }
}

extern "C" void kernel_launch(void* const* d_in, const int* in_sizes, int n_in,
                              void* d_out, int out_size) {
    const int*   etype = (const int*)  d_in[0];
    const float* etime = (const float*)d_in[1];
    // d_in[2] = arrival_times (unused by reference)
    const float* Wt    = (const float*)d_in[3];
    const float* temb  = (const float*)d_in[4];
    const float* wl    = (const float*)d_in[5];
    const float* p_bl  = (const float*)d_in[6];
    const float* wg    = (const float*)d_in[7];
    const float* p_bg  = (const float*)d_in[8];

    float* out = (float*)d_out;
    const size_t scoresN = (size_t)B_SZ * L_SZ * L_SZ;
    const size_t hidN    = (size_t)B_SZ * L_SZ * HID;
    float* out_scores = out;
    float* out_hidden = out + scoresN;
    float* out_tdiff  = out + scoresN + hidN;

    fused_kernel<<<TOTAL_BLOCKS, 256>>>(
        etype, etime, Wt, temb, wl, wg, p_bl, p_bg,
        out_scores, out_hidden, out_tdiff);
}